// round 12
// baseline (speedup 1.0000x reference)
#include <cuda_runtime.h>
#include <cstdint>

// SM-2 scan: R5 champion geometry (128 thr / 4 warps / 2 rows/thread,
// CHUNK=16, 2-stage cp.async double buffer) with the pad-20 layout replaced
// by an unpadded stride-16 + SW64-style XOR swizzle (addr ^= (8r)&0x30):
// 32KB smem/block -> 6 blocks/SM (24 warps) at unchanged ILP and sync
// structure. Swizzled LDS.128 pattern is conflict-free (lane word-starts
// {0,18,4,22,8,26,12,30} mod 32) and was HW-validated in the R7 TMA variant.
// Step function is R5 verbatim (R6/R10/R11 step rewrites all regressed).

static constexpr int STEPS          = 400;
static constexpr int RPW            = 64;
static constexpr int WARPS          = 4;
static constexpr int THREADS        = 32 * WARPS;          // 128
static constexpr int ROWS_PER_BLOCK = RPW * WARPS;         // 256
static constexpr int CHUNK          = 16;
static constexpr int NCHUNK         = STEPS / CHUNK;       // 25 exact
static constexpr int WBUF           = RPW * CHUNK;         // 1024 floats (no pad)
static constexpr int SMEM_BYTES     = WARPS * 2 * WBUF * (int)sizeof(float); // 32768

__device__ __forceinline__ uint32_t smem_u32(const void* p) {
    return (uint32_t)__cvta_generic_to_shared(p);
}
__device__ __forceinline__ void cp_async16(uint32_t saddr, const void* gptr) {
    asm volatile("cp.async.cg.shared.global [%0], [%1], 16;\n" :: "r"(saddr), "l"(gptr));
}
__device__ __forceinline__ void cp_commit() {
    asm volatile("cp.async.commit_group;\n" ::: "memory");
}
template <int N>
__device__ __forceinline__ void cp_wait() {
    asm volatile("cp.async.wait_group %0;\n" :: "n"(N) : "memory");
}

// Packed f32x2 helpers (sm_103a FFMA2/FMUL2/FADD2 via PTX).
union F2 { float f[2]; unsigned long long u; };
__device__ __forceinline__ F2 mk2(float a, float b) { F2 r; r.f[0] = a; r.f[1] = b; return r; }
__device__ __forceinline__ F2 mul2(F2 a, F2 b) {
    F2 d; asm("mul.rn.f32x2 %0, %1, %2;" : "=l"(d.u) : "l"(a.u), "l"(b.u)); return d;
}
__device__ __forceinline__ F2 add2(F2 a, F2 b) {
    F2 d; asm("add.rn.f32x2 %0, %1, %2;" : "=l"(d.u) : "l"(a.u), "l"(b.u)); return d;
}
__device__ __forceinline__ F2 fma2(F2 a, F2 b, F2 c) {
    F2 d; asm("fma.rn.f32x2 %0, %1, %2, %3;" : "=l"(d.u) : "l"(a.u), "l"(b.u), "l"(c.u)); return d;
}

// R5 step verbatim (proven fastest): R = interval a correct answer yields
// next step; R==1 <=> prev incorrect (exact: product path >= 1.3). Upper
// clamp deferred to output (EF >= 1.3 keeps the product monotone in a run).
__device__ __forceinline__ void sm2_step2(float pa, float pb, F2& I, F2& EF, F2& R) {
    const bool ca = pa >= 0.6f;          // == (p*5 >= 3) in RN
    const bool cb = pb >= 0.6f;

    float Ia = ca ? R.f[0] : 1.0f;
    float Ib = cb ? R.f[1] : 1.0f;

    F2 p = mk2(pa, pb);
    F2 w = fma2(p, mk2(-0.5f, -0.5f), mk2(1.4f, 1.4f));
    F2 u = fma2(p, w, mk2(-0.8f, -0.8f));   // 0.1-(5-q)(0.08+(5-q)*0.02), q=5p
    F2 EFn = add2(EF, u);
    EFn.f[0] = fmaxf(EFn.f[0], 1.3f);
    EFn.f[1] = fmaxf(EFn.f[1], 1.3f);
    EF.f[0] = ca ? EFn.f[0] : EF.f[0];
    EF.f[1] = cb ? EFn.f[1] : EF.f[1];

    I = mk2(Ia, Ib);
    F2 t = mul2(I, EF);                  // I*EF with next step's entry values
    R.f[0] = ca ? ((R.f[0] == 1.0f) ? 6.0f : t.f[0]) : 1.0f;
    R.f[1] = cb ? ((R.f[1] == 1.0f) ? 6.0f : t.f[1]) : 1.0f;
}

__global__ void __launch_bounds__(THREADS, 6)
sm2_scan_kernel(const float* __restrict__ hist, float* __restrict__ out, int B) {
    __shared__ __align__(128) float sbuf[WARPS * 2 * WBUF];  // 32 KB static

    const int lane  = threadIdx.x & 31;
    const int warp  = threadIdx.x >> 5;
    const int wrow0 = blockIdx.x * ROWS_PER_BLOCK + warp * RPW;

    const uint32_t base0 = smem_u32(sbuf) + warp * (2 * WBUF * 4);
    const uint32_t base1 = base0 + WBUF * 4;

    const float* g = hist + (size_t)wrow0 * STEPS;
    const bool full = (wrow0 + RPW <= B);

    // Chunk load: 64 rows x 16 floats; iter s covers 8 rows, 4 x 16B per row
    // (64B contiguous gmem per row segment). Dest swizzled: (64r ^ (8r)&0x30) ^ 16k.
    auto load_chunk = [&](uint32_t base, int c0) {
        #pragma unroll
        for (int s = 0; s < 8; s++) {
            int f = s * 32 + lane;
            int r = f >> 2, k = f & 3;
            uint32_t off = ((uint32_t)(r << 6) ^ ((uint32_t)(8 * r) & 0x30u)) ^ (uint32_t)(k << 4);
            if (full || wrow0 + r < B)
                cp_async16(base + off, g + (size_t)r * STEPS + c0 + k * 4);
        }
    };

    // Read offsets: rows lane and lane+32 share the same XOR term.
    const uint32_t offa = ((uint32_t)(lane << 6)) ^ ((uint32_t)(8 * lane) & 0x30u);
    const uint32_t offb = offa + 2048u;

    F2 I  = mk2(1.0f, 1.0f);
    F2 EF = mk2(2.5f, 2.5f);
    F2 R  = mk2(1.0f, 1.0f);

    load_chunk(base0, 0);
    cp_commit();

    #pragma unroll 1
    for (int c = 0; c < NCHUNK; c++) {
        const uint32_t cur = (c & 1) ? base1 : base0;
        const uint32_t nxt = (c & 1) ? base0 : base1;
        if (c + 1 < NCHUNK) {
            load_chunk(nxt, (c + 1) * CHUNK);
            cp_commit();
            cp_wait<1>();
        } else {
            cp_wait<0>();
        }
        __syncwarp();

        #pragma unroll
        for (int j = 0; j < CHUNK / 4; j++) {
            float4 va, vb;
            asm("ld.shared.v4.f32 {%0,%1,%2,%3}, [%4];"
                : "=f"(va.x), "=f"(va.y), "=f"(va.z), "=f"(va.w)
                : "r"(cur + (offa ^ (uint32_t)(16 * j))));
            asm("ld.shared.v4.f32 {%0,%1,%2,%3}, [%4];"
                : "=f"(vb.x), "=f"(vb.y), "=f"(vb.z), "=f"(vb.w)
                : "r"(cur + (offb ^ (uint32_t)(16 * j))));
            sm2_step2(va.x, vb.x, I, EF, R);
            sm2_step2(va.y, vb.y, I, EF, R);
            sm2_step2(va.z, vb.z, I, EF, R);
            sm2_step2(va.w, vb.w, I, EF, R);
        }
        __syncwarp();          // protect cur before next iteration overwrites it
    }

    if (wrow0 + lane < B)      out[wrow0 + lane]      = fminf(I.f[0], 274.0f);
    if (wrow0 + lane + 32 < B) out[wrow0 + lane + 32] = fminf(I.f[1], 274.0f);
}

extern "C" void kernel_launch(void* const* d_in, const int* in_sizes, int n_in,
                              void* d_out, int out_size) {
    const float* hist = (const float*)d_in[0];
    float* out = (float*)d_out;
    int B = out_size;

    int blocks = (B + ROWS_PER_BLOCK - 1) / ROWS_PER_BLOCK;
    sm2_scan_kernel<<<blocks, THREADS>>>(hist, out, B);
}

// round 13
// speedup vs baseline: 1.0581x; 1.0581x over previous
#include <cuda_runtime.h>
#include <cstdint>

// SM-2 scan, CHAMPION (R5, 135.7us): warp-private double-buffered cp.async
// tiles + packed-f32x2 step, 2 rows/thread.
// hist_p: [B, 400] f32. Block = 128 threads = 4 warps; warp owns 64 rows
// (lane -> rows lane, lane+32). CHUNK=16 cols, stride-20 smem (conflict-free
// LDS.128), 2-stage double buffer, 40KB smem -> 5 blocks/SM.
//
// Recurrence reformulation (output-exact vs reference):
//   R = I a correct answer would yield next step.
//   incorrect: I=1, R=1
//   correct:   I=R ; EF=max(EF+u,1.3) ; R = (R_old==1) ? 6 : I*EF
//   (R==1 is exact: product path always >= 1.3)
// Upper clamp deferred to output (EF>=1.3 keeps product monotone in a run).
// correct = (p >= 0.6f) == (p*5 >= 3) under RN (tie 0.6f*5 rounds to 3.0).
// EF delta as polynomial: u = fma(p, fma(p,-0.5,1.4), -0.8).

static constexpr int STEPS          = 400;
static constexpr int RPW            = 64;                  // rows per warp
static constexpr int WARPS          = 4;
static constexpr int THREADS        = 32 * WARPS;          // 128
static constexpr int ROWS_PER_BLOCK = RPW * WARPS;         // 256
static constexpr int CHUNK          = 16;                  // floats per chunk
static constexpr int NCHUNK         = STEPS / CHUNK;       // 25 exact
static constexpr int STRIDE         = CHUNK + 4;           // 20: conflict-free LDS.128
static constexpr int WBUF           = RPW * STRIDE;        // 1280 floats
static constexpr int SMEM_BYTES     = WARPS * 2 * WBUF * (int)sizeof(float); // 40960

__device__ __forceinline__ uint32_t smem_u32(const void* p) {
    return (uint32_t)__cvta_generic_to_shared(p);
}
__device__ __forceinline__ void cp_async16(uint32_t saddr, const void* gptr) {
    asm volatile("cp.async.cg.shared.global [%0], [%1], 16;\n" :: "r"(saddr), "l"(gptr));
}
__device__ __forceinline__ void cp_commit() {
    asm volatile("cp.async.commit_group;\n" ::: "memory");
}
template <int N>
__device__ __forceinline__ void cp_wait() {
    asm volatile("cp.async.wait_group %0;\n" :: "n"(N) : "memory");
}

// Packed f32x2 helpers (sm_103a FFMA2/FMUL2/FADD2 via PTX).
union F2 { float f[2]; unsigned long long u; };
__device__ __forceinline__ F2 mk2(float a, float b) { F2 r; r.f[0] = a; r.f[1] = b; return r; }
__device__ __forceinline__ F2 mul2(F2 a, F2 b) {
    F2 d; asm("mul.rn.f32x2 %0, %1, %2;" : "=l"(d.u) : "l"(a.u), "l"(b.u)); return d;
}
__device__ __forceinline__ F2 add2(F2 a, F2 b) {
    F2 d; asm("add.rn.f32x2 %0, %1, %2;" : "=l"(d.u) : "l"(a.u), "l"(b.u)); return d;
}
__device__ __forceinline__ F2 fma2(F2 a, F2 b, F2 c) {
    F2 d; asm("fma.rn.f32x2 %0, %1, %2, %3;" : "=l"(d.u) : "l"(a.u), "l"(b.u), "l"(c.u)); return d;
}

// One step for two independent rows.
__device__ __forceinline__ void sm2_step2(float pa, float pb, F2& I, F2& EF, F2& R) {
    const bool ca = pa >= 0.6f;          // == (p*5 >= 3) in RN
    const bool cb = pb >= 0.6f;

    float Ia = ca ? R.f[0] : 1.0f;
    float Ib = cb ? R.f[1] : 1.0f;

    F2 p = mk2(pa, pb);
    F2 w = fma2(p, mk2(-0.5f, -0.5f), mk2(1.4f, 1.4f));
    F2 u = fma2(p, w, mk2(-0.8f, -0.8f));      // 0.1-(5-q)(0.08+(5-q)*0.02), q=5p
    F2 EFn = add2(EF, u);
    EFn.f[0] = fmaxf(EFn.f[0], 1.3f);
    EFn.f[1] = fmaxf(EFn.f[1], 1.3f);
    EF.f[0] = ca ? EFn.f[0] : EF.f[0];
    EF.f[1] = cb ? EFn.f[1] : EF.f[1];

    I = mk2(Ia, Ib);
    F2 t = mul2(I, EF);                        // I*EF with next step's entry values
    R.f[0] = ca ? ((R.f[0] == 1.0f) ? 6.0f : t.f[0]) : 1.0f;
    R.f[1] = cb ? ((R.f[1] == 1.0f) ? 6.0f : t.f[1]) : 1.0f;
}

extern __shared__ float sbuf[];

__global__ void __launch_bounds__(THREADS, 5)
sm2_scan_kernel(const float* __restrict__ hist, float* __restrict__ out, int B) {
    const int lane  = threadIdx.x & 31;
    const int warp  = threadIdx.x >> 5;
    const int wrow0 = blockIdx.x * ROWS_PER_BLOCK + warp * RPW;

    float* buf0 = sbuf + warp * (2 * WBUF);
    float* buf1 = buf0 + WBUF;

    const float* g = hist + (size_t)wrow0 * STEPS;
    const bool full = (wrow0 + RPW <= B);

    // Chunk load: 64 rows x 16 floats; iter s covers 8 rows, 4 f4/row
    // (64B contiguous gmem per row segment).
    auto load_chunk = [&](float* buf, int c0) {
        #pragma unroll
        for (int s = 0; s < 8; s++) {
            int f = s * 32 + lane;
            int r = f >> 2, k = f & 3;
            if (full || wrow0 + r < B)
                cp_async16(smem_u32(buf + r * STRIDE + k * 4),
                           g + (size_t)r * STEPS + c0 + k * 4);
        }
    };

    F2 I  = mk2(1.0f, 1.0f);
    F2 EF = mk2(2.5f, 2.5f);
    F2 R  = mk2(1.0f, 1.0f);

    load_chunk(buf0, 0);
    cp_commit();

    const int ra = lane, rb = lane + 32;
    const bool livea = full || (wrow0 + ra < B);
    const bool liveb = full || (wrow0 + rb < B);

    #pragma unroll 1
    for (int c = 0; c < NCHUNK; c++) {
        float* cur = (c & 1) ? buf1 : buf0;
        float* nxt = (c & 1) ? buf0 : buf1;
        if (c + 1 < NCHUNK) {
            load_chunk(nxt, (c + 1) * CHUNK);
            cp_commit();
            cp_wait<1>();      // chunk c complete (this lane's copies)
        } else {
            cp_wait<0>();
        }
        __syncwarp();          // peer lanes' copies visible warp-wide

        const float* ma = cur + ra * STRIDE;
        const float* mb = cur + rb * STRIDE;
        #pragma unroll
        for (int j = 0; j < CHUNK / 4; j++) {
            float4 va = *reinterpret_cast<const float4*>(ma + 4 * j);
            float4 vb = *reinterpret_cast<const float4*>(mb + 4 * j);
            sm2_step2(va.x, vb.x, I, EF, R);
            sm2_step2(va.y, vb.y, I, EF, R);
            sm2_step2(va.z, vb.z, I, EF, R);
            sm2_step2(va.w, vb.w, I, EF, R);
        }
        __syncwarp();          // protect cur before it is overwritten
    }

    if (livea) out[wrow0 + ra] = fminf(I.f[0], 274.0f);  // h_t = I, deferred clamp
    if (liveb) out[wrow0 + rb] = fminf(I.f[1], 274.0f);
}

extern "C" void kernel_launch(void* const* d_in, const int* in_sizes, int n_in,
                              void* d_out, int out_size) {
    const float* hist = (const float*)d_in[0];
    float* out = (float*)d_out;
    int B = out_size;

    cudaFuncSetAttribute(sm2_scan_kernel,
                         cudaFuncAttributeMaxDynamicSharedMemorySize, SMEM_BYTES);

    int blocks = (B + ROWS_PER_BLOCK - 1) / ROWS_PER_BLOCK;
    sm2_scan_kernel<<<blocks, THREADS, SMEM_BYTES>>>(hist, out, B);
}

// round 14
// speedup vs baseline: 1.0590x; 1.0009x over previous
#include <cuda_runtime.h>
#include <cstdint>

// SM-2 scan, CHAMPION (R5 = R13, best draw 135.7us): warp-private
// double-buffered cp.async tiles + packed-f32x2 step, 2 rows/thread.
// hist_p: [B, 400] f32. Block = 128 threads = 4 warps; warp owns 64 rows
// (lane -> rows lane, lane+32). CHUNK=16 cols, stride-20 smem (conflict-free
// LDS.128), 2-stage double buffer, 40KB smem -> 5 blocks/SM.
//
// NOTE (session record): this exact source measured 135.7us (R5) and 147.6us
// (R13) — run-to-run variance on identical code is ~9%. All structural
// perturbations tried (TMA ring, persistent grid, 1 or 4 rows/thread,
// fma-select / predicate-carry step rewrites, XOR-swizzle layout, L2 hints)
// had equal-or-worse distributions; the two mechanism-confirmed movers were
// strict losers (persistent grid: in-flight-load collapse; XOR swizzle:
// alu-pipe 75%). This geometry+step is the measured optimum.
//
// Recurrence reformulation (output-exact vs reference):
//   R = I a correct answer would yield next step.
//   incorrect: I=1, R=1
//   correct:   I=R ; EF=max(EF+u,1.3) ; R = (R_old==1) ? 6 : I*EF
//   (R==1 is exact: product path always >= 1.3)
// Upper clamp deferred to output (EF>=1.3 keeps product monotone in a run).
// correct = (p >= 0.6f) == (p*5 >= 3) under RN (tie 0.6f*5 rounds to 3.0).
// EF delta as polynomial: u = fma(p, fma(p,-0.5,1.4), -0.8).

static constexpr int STEPS          = 400;
static constexpr int RPW            = 64;                  // rows per warp
static constexpr int WARPS          = 4;
static constexpr int THREADS        = 32 * WARPS;          // 128
static constexpr int ROWS_PER_BLOCK = RPW * WARPS;         // 256
static constexpr int CHUNK          = 16;                  // floats per chunk
static constexpr int NCHUNK         = STEPS / CHUNK;       // 25 exact
static constexpr int STRIDE         = CHUNK + 4;           // 20: conflict-free LDS.128
static constexpr int WBUF           = RPW * STRIDE;        // 1280 floats
static constexpr int SMEM_BYTES     = WARPS * 2 * WBUF * (int)sizeof(float); // 40960

__device__ __forceinline__ uint32_t smem_u32(const void* p) {
    return (uint32_t)__cvta_generic_to_shared(p);
}
__device__ __forceinline__ void cp_async16(uint32_t saddr, const void* gptr) {
    asm volatile("cp.async.cg.shared.global [%0], [%1], 16;\n" :: "r"(saddr), "l"(gptr));
}
__device__ __forceinline__ void cp_commit() {
    asm volatile("cp.async.commit_group;\n" ::: "memory");
}
template <int N>
__device__ __forceinline__ void cp_wait() {
    asm volatile("cp.async.wait_group %0;\n" :: "n"(N) : "memory");
}

// Packed f32x2 helpers (sm_103a FFMA2/FMUL2/FADD2 via PTX).
union F2 { float f[2]; unsigned long long u; };
__device__ __forceinline__ F2 mk2(float a, float b) { F2 r; r.f[0] = a; r.f[1] = b; return r; }
__device__ __forceinline__ F2 mul2(F2 a, F2 b) {
    F2 d; asm("mul.rn.f32x2 %0, %1, %2;" : "=l"(d.u) : "l"(a.u), "l"(b.u)); return d;
}
__device__ __forceinline__ F2 add2(F2 a, F2 b) {
    F2 d; asm("add.rn.f32x2 %0, %1, %2;" : "=l"(d.u) : "l"(a.u), "l"(b.u)); return d;
}
__device__ __forceinline__ F2 fma2(F2 a, F2 b, F2 c) {
    F2 d; asm("fma.rn.f32x2 %0, %1, %2, %3;" : "=l"(d.u) : "l"(a.u), "l"(b.u), "l"(c.u)); return d;
}

// One step for two independent rows.
__device__ __forceinline__ void sm2_step2(float pa, float pb, F2& I, F2& EF, F2& R) {
    const bool ca = pa >= 0.6f;          // == (p*5 >= 3) in RN
    const bool cb = pb >= 0.6f;

    float Ia = ca ? R.f[0] : 1.0f;
    float Ib = cb ? R.f[1] : 1.0f;

    F2 p = mk2(pa, pb);
    F2 w = fma2(p, mk2(-0.5f, -0.5f), mk2(1.4f, 1.4f));
    F2 u = fma2(p, w, mk2(-0.8f, -0.8f));      // 0.1-(5-q)(0.08+(5-q)*0.02), q=5p
    F2 EFn = add2(EF, u);
    EFn.f[0] = fmaxf(EFn.f[0], 1.3f);
    EFn.f[1] = fmaxf(EFn.f[1], 1.3f);
    EF.f[0] = ca ? EFn.f[0] : EF.f[0];
    EF.f[1] = cb ? EFn.f[1] : EF.f[1];

    I = mk2(Ia, Ib);
    F2 t = mul2(I, EF);                        // I*EF with next step's entry values
    R.f[0] = ca ? ((R.f[0] == 1.0f) ? 6.0f : t.f[0]) : 1.0f;
    R.f[1] = cb ? ((R.f[1] == 1.0f) ? 6.0f : t.f[1]) : 1.0f;
}

extern __shared__ float sbuf[];

__global__ void __launch_bounds__(THREADS, 5)
sm2_scan_kernel(const float* __restrict__ hist, float* __restrict__ out, int B) {
    const int lane  = threadIdx.x & 31;
    const int warp  = threadIdx.x >> 5;
    const int wrow0 = blockIdx.x * ROWS_PER_BLOCK + warp * RPW;

    float* buf0 = sbuf + warp * (2 * WBUF);
    float* buf1 = buf0 + WBUF;

    const float* g = hist + (size_t)wrow0 * STEPS;
    const bool full = (wrow0 + RPW <= B);

    // Chunk load: 64 rows x 16 floats; iter s covers 8 rows, 4 f4/row
    // (64B contiguous gmem per row segment).
    auto load_chunk = [&](float* buf, int c0) {
        #pragma unroll
        for (int s = 0; s < 8; s++) {
            int f = s * 32 + lane;
            int r = f >> 2, k = f & 3;
            if (full || wrow0 + r < B)
                cp_async16(smem_u32(buf + r * STRIDE + k * 4),
                           g + (size_t)r * STEPS + c0 + k * 4);
        }
    };

    F2 I  = mk2(1.0f, 1.0f);
    F2 EF = mk2(2.5f, 2.5f);
    F2 R  = mk2(1.0f, 1.0f);

    load_chunk(buf0, 0);
    cp_commit();

    const int ra = lane, rb = lane + 32;
    const bool livea = full || (wrow0 + ra < B);
    const bool liveb = full || (wrow0 + rb < B);

    #pragma unroll 1
    for (int c = 0; c < NCHUNK; c++) {
        float* cur = (c & 1) ? buf1 : buf0;
        float* nxt = (c & 1) ? buf0 : buf1;
        if (c + 1 < NCHUNK) {
            load_chunk(nxt, (c + 1) * CHUNK);
            cp_commit();
            cp_wait<1>();      // chunk c complete (this lane's copies)
        } else {
            cp_wait<0>();
        }
        __syncwarp();          // peer lanes' copies visible warp-wide

        const float* ma = cur + ra * STRIDE;
        const float* mb = cur + rb * STRIDE;
        #pragma unroll
        for (int j = 0; j < CHUNK / 4; j++) {
            float4 va = *reinterpret_cast<const float4*>(ma + 4 * j);
            float4 vb = *reinterpret_cast<const float4*>(mb + 4 * j);
            sm2_step2(va.x, vb.x, I, EF, R);
            sm2_step2(va.y, vb.y, I, EF, R);
            sm2_step2(va.z, vb.z, I, EF, R);
            sm2_step2(va.w, vb.w, I, EF, R);
        }
        __syncwarp();          // protect cur before it is overwritten
    }

    if (livea) out[wrow0 + ra] = fminf(I.f[0], 274.0f);  // h_t = I, deferred clamp
    if (liveb) out[wrow0 + rb] = fminf(I.f[1], 274.0f);
}

extern "C" void kernel_launch(void* const* d_in, const int* in_sizes, int n_in,
                              void* d_out, int out_size) {
    const float* hist = (const float*)d_in[0];
    float* out = (float*)d_out;
    int B = out_size;

    cudaFuncSetAttribute(sm2_scan_kernel,
                         cudaFuncAttributeMaxDynamicSharedMemorySize, SMEM_BYTES);

    int blocks = (B + ROWS_PER_BLOCK - 1) / ROWS_PER_BLOCK;
    sm2_scan_kernel<<<blocks, THREADS, SMEM_BYTES>>>(hist, out, B);
}

// round 15
// speedup vs baseline: 1.0602x; 1.0011x over previous
#include <cuda_runtime.h>
#include <cstdint>

// SM-2 scan, champion geometry (R5: 128 thr / 4 warps / 2 rows/thread,
// CHUNK=16, stride-20, 2-stage cp.async double buffer, 5 blocks/SM) with
// chunk-body LDS hoisting: all 8 LDS.128 of a chunk issue back-to-back at
// the top (MLP=8, single drain), then 16 steps run purely from registers.
//
// Session record: identical champion source drew {135.7, 147.6, 147.5}us —
// environment (clock state) shifted mid-session; ~9% run-to-run variance.
//
// Recurrence reformulation (output-exact vs reference):
//   R = I a correct answer would yield next step.
//   incorrect: I=1, R=1
//   correct:   I=R ; EF=max(EF+u,1.3) ; R = (R_old==1) ? 6 : I*EF
//   (R==1 exact: product path always >= 1.3)
// Upper clamp deferred to output (EF>=1.3 keeps product monotone in a run).
// correct = (p >= 0.6f) == (p*5 >= 3) under RN. u = fma(p, fma(p,-.5,1.4), -.8).

static constexpr int STEPS          = 400;
static constexpr int RPW            = 64;
static constexpr int WARPS          = 4;
static constexpr int THREADS        = 32 * WARPS;          // 128
static constexpr int ROWS_PER_BLOCK = RPW * WARPS;         // 256
static constexpr int CHUNK          = 16;
static constexpr int NCHUNK         = STEPS / CHUNK;       // 25 exact
static constexpr int STRIDE         = CHUNK + 4;           // 20: conflict-free LDS.128
static constexpr int WBUF           = RPW * STRIDE;        // 1280 floats
static constexpr int SMEM_BYTES     = WARPS * 2 * WBUF * (int)sizeof(float); // 40960

__device__ __forceinline__ uint32_t smem_u32(const void* p) {
    return (uint32_t)__cvta_generic_to_shared(p);
}
__device__ __forceinline__ void cp_async16(uint32_t saddr, const void* gptr) {
    asm volatile("cp.async.cg.shared.global [%0], [%1], 16;\n" :: "r"(saddr), "l"(gptr));
}
__device__ __forceinline__ void cp_commit() {
    asm volatile("cp.async.commit_group;\n" ::: "memory");
}
template <int N>
__device__ __forceinline__ void cp_wait() {
    asm volatile("cp.async.wait_group %0;\n" :: "n"(N) : "memory");
}

// Packed f32x2 helpers (sm_103a FFMA2/FMUL2/FADD2 via PTX).
union F2 { float f[2]; unsigned long long u; };
__device__ __forceinline__ F2 mk2(float a, float b) { F2 r; r.f[0] = a; r.f[1] = b; return r; }
__device__ __forceinline__ F2 mul2(F2 a, F2 b) {
    F2 d; asm("mul.rn.f32x2 %0, %1, %2;" : "=l"(d.u) : "l"(a.u), "l"(b.u)); return d;
}
__device__ __forceinline__ F2 add2(F2 a, F2 b) {
    F2 d; asm("add.rn.f32x2 %0, %1, %2;" : "=l"(d.u) : "l"(a.u), "l"(b.u)); return d;
}
__device__ __forceinline__ F2 fma2(F2 a, F2 b, F2 c) {
    F2 d; asm("fma.rn.f32x2 %0, %1, %2, %3;" : "=l"(d.u) : "l"(a.u), "l"(b.u), "l"(c.u)); return d;
}

// One step for two independent rows (R5 step verbatim).
__device__ __forceinline__ void sm2_step2(float pa, float pb, F2& I, F2& EF, F2& R) {
    const bool ca = pa >= 0.6f;          // == (p*5 >= 3) in RN
    const bool cb = pb >= 0.6f;

    float Ia = ca ? R.f[0] : 1.0f;
    float Ib = cb ? R.f[1] : 1.0f;

    F2 p = mk2(pa, pb);
    F2 w = fma2(p, mk2(-0.5f, -0.5f), mk2(1.4f, 1.4f));
    F2 u = fma2(p, w, mk2(-0.8f, -0.8f));      // 0.1-(5-q)(0.08+(5-q)*0.02), q=5p
    F2 EFn = add2(EF, u);
    EFn.f[0] = fmaxf(EFn.f[0], 1.3f);
    EFn.f[1] = fmaxf(EFn.f[1], 1.3f);
    EF.f[0] = ca ? EFn.f[0] : EF.f[0];
    EF.f[1] = cb ? EFn.f[1] : EF.f[1];

    I = mk2(Ia, Ib);
    F2 t = mul2(I, EF);                        // I*EF with next step's entry values
    R.f[0] = ca ? ((R.f[0] == 1.0f) ? 6.0f : t.f[0]) : 1.0f;
    R.f[1] = cb ? ((R.f[1] == 1.0f) ? 6.0f : t.f[1]) : 1.0f;
}

extern __shared__ float sbuf[];

__global__ void __launch_bounds__(THREADS, 5)
sm2_scan_kernel(const float* __restrict__ hist, float* __restrict__ out, int B) {
    const int lane  = threadIdx.x & 31;
    const int warp  = threadIdx.x >> 5;
    const int wrow0 = blockIdx.x * ROWS_PER_BLOCK + warp * RPW;

    float* buf0 = sbuf + warp * (2 * WBUF);
    float* buf1 = buf0 + WBUF;

    const float* g = hist + (size_t)wrow0 * STEPS;
    const bool full = (wrow0 + RPW <= B);

    // Chunk load: 64 rows x 16 floats; iter s covers 8 rows, 4 f4/row
    // (64B contiguous gmem per row segment).
    auto load_chunk = [&](float* buf, int c0) {
        #pragma unroll
        for (int s = 0; s < 8; s++) {
            int f = s * 32 + lane;
            int r = f >> 2, k = f & 3;
            if (full || wrow0 + r < B)
                cp_async16(smem_u32(buf + r * STRIDE + k * 4),
                           g + (size_t)r * STEPS + c0 + k * 4);
        }
    };

    F2 I  = mk2(1.0f, 1.0f);
    F2 EF = mk2(2.5f, 2.5f);
    F2 R  = mk2(1.0f, 1.0f);

    load_chunk(buf0, 0);
    cp_commit();

    const int ra = lane, rb = lane + 32;
    const bool livea = full || (wrow0 + ra < B);
    const bool liveb = full || (wrow0 + rb < B);

    #pragma unroll 1
    for (int c = 0; c < NCHUNK; c++) {
        float* cur = (c & 1) ? buf1 : buf0;
        float* nxt = (c & 1) ? buf0 : buf1;
        if (c + 1 < NCHUNK) {
            load_chunk(nxt, (c + 1) * CHUNK);
            cp_commit();
            cp_wait<1>();      // chunk c complete (this lane's copies)
        } else {
            cp_wait<0>();
        }
        __syncwarp();          // peer lanes' copies visible warp-wide

        // Front-batch ALL chunk reads (8x LDS.128, MLP=8), then compute
        // the 16 steps purely from registers.
        const float* ma = cur + ra * STRIDE;
        const float* mb = cur + rb * STRIDE;
        float4 va[4], vb[4];
        #pragma unroll
        for (int j = 0; j < 4; j++) {
            va[j] = *reinterpret_cast<const float4*>(ma + 4 * j);
            vb[j] = *reinterpret_cast<const float4*>(mb + 4 * j);
        }

        #pragma unroll
        for (int j = 0; j < 4; j++) {
            sm2_step2(va[j].x, vb[j].x, I, EF, R);
            sm2_step2(va[j].y, vb[j].y, I, EF, R);
            sm2_step2(va[j].z, vb[j].z, I, EF, R);
            sm2_step2(va[j].w, vb[j].w, I, EF, R);
        }
        __syncwarp();          // protect cur before it is overwritten
    }

    if (livea) out[wrow0 + ra] = fminf(I.f[0], 274.0f);  // h_t = I, deferred clamp
    if (liveb) out[wrow0 + rb] = fminf(I.f[1], 274.0f);
}

extern "C" void kernel_launch(void* const* d_in, const int* in_sizes, int n_in,
                              void* d_out, int out_size) {
    const float* hist = (const float*)d_in[0];
    float* out = (float*)d_out;
    int B = out_size;

    cudaFuncSetAttribute(sm2_scan_kernel,
                         cudaFuncAttributeMaxDynamicSharedMemorySize, SMEM_BYTES);

    int blocks = (B + ROWS_PER_BLOCK - 1) / ROWS_PER_BLOCK;
    sm2_scan_kernel<<<blocks, THREADS, SMEM_BYTES>>>(hist, out, B);
}